// round 5
// baseline (speedup 1.0000x reference)
#include <cuda_runtime.h>
#include <cuda_bf16.h>

#define NMAX 100000
#define EMAX 800000

// ---------------- scratch (device globals; no runtime allocation) ------------
__device__ float4 g_h2  [NMAX * 6];    // [N,24] padded (23 + 1 zero)
__device__ float4 g_q1  [NMAX * 48];   // [N,192]
__device__ float4 g_kv1 [NMAX * 96];   // [N,384]: k | v per node
__device__ float4 g_acc1[NMAX * 48];   // skip, then conv1 out (pre-elu)
__device__ float4 g_q2  [NMAX * 16];   // [N,64]
__device__ float4 g_kv2 [NMAX * 32];   // [N,128]: k | v
__device__ float4 g_acc2[NMAX * 16];   // conv2 out (pre-elu)
// CSR scratch
__device__ int  g_deg   [NMAX];
__device__ int  g_part  [NMAX];
__device__ int  g_bsum  [512];
__device__ int  g_rowptr[NMAX];
__device__ int  g_cursor[NMAX];
__device__ int2 g_cpack [EMAX];        // (src, edge_id) grouped by dst

__device__ __forceinline__ float eluf(float x) { return x > 0.f ? x : expm1f(x); }

// ---------------- CSR build ---------------------------------------------------
__global__ void k_zero(int n) {
    int i = blockIdx.x * blockDim.x + threadIdx.x;
    if (i < n) g_deg[i] = 0;
}
__global__ void k_count(const int* __restrict__ dst, int E) {
    int e = blockIdx.x * blockDim.x + threadIdx.x;
    if (e < E) atomicAdd(&g_deg[dst[e]], 1);
}
__global__ void k_scanA(int n) {                 // 256 threads/block
    __shared__ int s[256];
    int tid = threadIdx.x, i = blockIdx.x * 256 + tid;
    int v = (i < n) ? g_deg[i] : 0;
    s[tid] = v; __syncthreads();
    #pragma unroll
    for (int off = 1; off < 256; off <<= 1) {
        int t = (tid >= off) ? s[tid - off] : 0;
        __syncthreads();
        s[tid] += t;
        __syncthreads();
    }
    if (i < n) g_part[i] = s[tid] - v;           // exclusive within block
    if (tid == 255) g_bsum[blockIdx.x] = s[255];
}
__global__ void k_scanB(int nb) {                // single block, 512 threads
    __shared__ int s[512];
    int tid = threadIdx.x;
    int v = (tid < nb) ? g_bsum[tid] : 0;
    s[tid] = v; __syncthreads();
    #pragma unroll
    for (int off = 1; off < 512; off <<= 1) {
        int t = (tid >= off) ? s[tid - off] : 0;
        __syncthreads();
        s[tid] += t;
        __syncthreads();
    }
    g_bsum[tid] = s[tid] - v;                    // exclusive block offsets
}
__global__ void k_scanC(int n) {
    int i = blockIdx.x * blockDim.x + threadIdx.x;
    if (i < n) {
        int r = g_part[i] + g_bsum[i >> 8];
        g_rowptr[i] = r;
        g_cursor[i] = r;
    }
}
__global__ void k_scatter(const int* __restrict__ src, const int* __restrict__ dst, int E) {
    int e = blockIdx.x * blockDim.x + threadIdx.x;
    if (e < E) {
        int d = dst[e];
        int pos = atomicAdd(&g_cursor[d], 1);
        g_cpack[pos] = make_int2(src[e], e);
    }
}

// ---------------- h2 = elu(elu(x@A+bA)@B+bB), padded to 24 -------------------
__global__ void k_h2(const float* __restrict__ x,
                     const float* __restrict__ Aw, const float* __restrict__ Ab,
                     const float* __restrict__ Bw, const float* __restrict__ Bb,
                     int n) {
    __shared__ float sA[23 * 23], sB[23 * 23], sbA[23], sbB[23];
    __shared__ float sx[256 * 23];
    int tid = threadIdx.x;
    for (int i = tid; i < 23 * 23; i += 256) { sA[i] = Aw[i]; sB[i] = Bw[i]; }
    if (tid < 23) { sbA[tid] = Ab[tid]; sbB[tid] = Bb[tid]; }
    int base = blockIdx.x * 256;
    int cnt  = min(256, n - base);
    for (int i = tid; i < cnt * 23; i += 256) sx[i] = x[base * 23 + i];
    __syncthreads();
    if (tid < cnt) {
        const float* xr = &sx[tid * 23];
        float h1[23];
        #pragma unroll
        for (int j = 0; j < 23; j++) {
            float a = sbA[j];
            #pragma unroll
            for (int k = 0; k < 23; k++) a += xr[k] * sA[k * 23 + j];
            h1[j] = eluf(a);
        }
        float* out = (float*)g_h2 + (base + tid) * 24;
        #pragma unroll
        for (int j = 0; j < 23; j++) {
            float a = sbB[j];
            #pragma unroll
            for (int k = 0; k < 23; k++) a += h1[k] * sB[k * 23 + j];
            out[j] = eluf(a);
        }
        out[23] = 0.f;
    }
}

// ---------------- conv1 node GEMM: [N,24]@[24,768] ----------------------------
__global__ void k_gemm1(const float* __restrict__ qw, const float* __restrict__ qb,
                        const float* __restrict__ kw, const float* __restrict__ kb,
                        const float* __restrict__ vw, const float* __restrict__ vb,
                        const float* __restrict__ sw, const float* __restrict__ sb,
                        int n) {
    __shared__ float4 sh[128 * 6];
    int tid = threadIdx.x;                  // 768 threads
    int arr = tid / 192, cc = tid % 192;
    const float* W = arr == 0 ? qw : arr == 1 ? kw : arr == 2 ? vw : sw;
    const float* B = arr == 0 ? qb : arr == 1 ? kb : arr == 2 ? vb : sb;
    float w[24];
    #pragma unroll
    for (int k = 0; k < 23; k++) w[k] = W[k * 192 + cc];
    w[23] = 0.f;
    float bias = B[cc];
    int base = blockIdx.x * 128;
    int cnt  = min(128, n - base);
    for (int i = tid; i < cnt * 6; i += 768) sh[i] = g_h2[base * 6 + i];
    __syncthreads();
    for (int nn = 0; nn < cnt; nn++) {
        float a = bias;
        #pragma unroll
        for (int k4 = 0; k4 < 6; k4++) {
            float4 h = sh[nn * 6 + k4];
            a += h.x * w[4 * k4] + h.y * w[4 * k4 + 1] + h.z * w[4 * k4 + 2] + h.w * w[4 * k4 + 3];
        }
        int node = base + nn;
        if (arr == 0)      ((float*)g_q1)[node * 192 + cc] = a;
        else if (arr == 1) ((float*)g_kv1)[node * 384 + cc] = a;
        else if (arr == 2) ((float*)g_kv1)[node * 384 + 192 + cc] = a;
        else               ((float*)g_acc1)[node * 192 + cc] = a;
    }
}

// ---------------- conv1: node-centric fused softmax-aggregate -----------------
// warp per dst node; float4-contiguous gathers; head-sums via per-warp smem.
// NOTE: f2 is CLAMPED for lanes >= 16 so that every load address is in-bounds
// for all lanes (nvcc may speculate loads out of ternaries/ifs). Stores that
// must not duplicate are guarded by hasB (stores are never speculated).
__global__ void k_conv1(const float* __restrict__ ea, const float* __restrict__ ew, int n) {
    __shared__ float4 sW4[336];             // e1_w as [7][48] float4
    __shared__ float  sP[8][48];            // per-warp dot partials
    int tid = threadIdx.x;
    { float* sWf = (float*)sW4;
      for (int i = tid; i < 1344; i += 256) sWf[i] = ew[i]; }
    __syncthreads();
    int warp = tid >> 5, lane = tid & 31;
    int node = blockIdx.x * 8 + warp;
    if (node >= n) return;
    int deg = g_deg[node];
    if (deg == 0) return;                   // acc1 already holds skip
    int rs = g_rowptr[node];
    bool hasB = lane < 16;
    int f1 = lane;
    int f2 = hasB ? (32 + lane) : lane;     // clamped: always < 48
    int hA = f1 / 6, hB = f2 / 6;           // head owning each float4 (<= 7)
    float* sPw = sP[warp];

    const float4* qbase = g_q1 + node * 48;
    float4 qA = qbase[f1];
    float4 qB = qbase[f2];                  // safe for all lanes now

    // pq[t] = q-row · We[t] per head (valid on lanes 0..7)
    float pq[7];
    #pragma unroll
    for (int t = 0; t < 7; t++) {
        const float4* wt = &sW4[t * 48];
        float4 wA = wt[f1];
        float4 wB = wt[f2];
        sPw[f1] = qA.x * wA.x + qA.y * wA.y + qA.z * wA.z + qA.w * wA.w;
        if (hasB)
            sPw[f2] = qB.x * wB.x + qB.y * wB.y + qB.z * wB.z + qB.w * wB.w;
        __syncwarp();
        float sum = 0.f;
        if (lane < 8) {
            const float* sp = &sPw[lane * 6];
            sum = sp[0] + sp[1] + sp[2] + sp[3] + sp[4] + sp[5];
        }
        pq[t] = sum;
        __syncwarp();
    }

    float4 accA = make_float4(0, 0, 0, 0), accB = make_float4(0, 0, 0, 0);
    float den = 0.f, a0 = 0.f, a1 = 0.f;
    int g = lane & 3;

    int2 se = g_cpack[rs];
    for (int i = 0; i < deg; i++) {
        int s = se.x, eid = se.y;
        if (i + 1 < deg) se = g_cpack[rs + i + 1];
        float eav[7];
        #pragma unroll
        for (int t = 0; t < 7; t++) eav[t] = __ldg(&ea[eid * 7 + t]);
        const float4* kv = g_kv1 + s * 96;
        float4 kA = kv[f1], vA = kv[48 + f1];
        float4 kB = kv[f2], vB = kv[48 + f2];   // in-bounds (f2 < 48)
        sPw[f1] = qA.x * kA.x + qA.y * kA.y + qA.z * kA.z + qA.w * kA.w;
        if (hasB)
            sPw[f2] = qB.x * kB.x + qB.y * kB.y + qB.z * kB.z + qB.w * kB.w;
        __syncwarp();
        float ex = 0.f;
        if (lane < 8) {
            const float* sp = &sPw[lane * 6];
            float lp = sp[0] + sp[1] + sp[2] + sp[3] + sp[4] + sp[5];
            #pragma unroll
            for (int t = 0; t < 7; t++) lp += eav[t] * pq[t];
            ex = __expf(lp * 0.20412414523193154f);   // 1/sqrt(24)
            den += ex;
        }
        __syncwarp();
        float exh = __shfl_sync(0xffffffffu, ex, lane >> 2);
        float elo = g == 0 ? eav[0] : g == 1 ? eav[2] : g == 2 ? eav[4] : eav[6];
        float ehi = g == 0 ? eav[1] : g == 1 ? eav[3] : g == 2 ? eav[5] : 0.f;
        a0 += exh * elo;
        a1 += exh * ehi;
        float exA = __shfl_sync(0xffffffffu, ex, hA);
        float exB = __shfl_sync(0xffffffffu, ex, hB);
        accA.x += exA * vA.x; accA.y += exA * vA.y;
        accA.z += exA * vA.z; accA.w += exA * vA.w;
        if (hasB) {
            accB.x += exB * vB.x; accB.y += exB * vB.y;
            accB.z += exB * vB.z; accB.w += exB * vB.w;
        }
    }

    float inv = (lane < 8) ? 1.f / den : 0.f;
    float invA = __shfl_sync(0xffffffffu, inv, hA);
    float invB = __shfl_sync(0xffffffffu, inv, hB);
    float aeA[7], aeB[7];
    #pragma unroll
    for (int t = 0; t < 7; t++) {
        int slA = hA * 4 + (t >> 1);            // <= 31
        float v0 = __shfl_sync(0xffffffffu, a0, slA);
        float v1 = __shfl_sync(0xffffffffu, a1, slA);
        aeA[t] = (t & 1) ? v1 : v0;
        int slB = hB * 4 + (t >> 1);            // <= 31 (hB <= 7)
        float u0 = __shfl_sync(0xffffffffu, a0, slB);
        float u1 = __shfl_sync(0xffffffffu, a1, slB);
        aeB[t] = (t & 1) ? u1 : u0;
    }
    float4 mA = accA;
    #pragma unroll
    for (int t = 0; t < 7; t++) {
        float4 w = sW4[t * 48 + f1];
        mA.x += aeA[t] * w.x; mA.y += aeA[t] * w.y;
        mA.z += aeA[t] * w.z; mA.w += aeA[t] * w.w;
    }
    float4* opA = g_acc1 + node * 48 + f1;
    float4 oA = *opA;
    oA.x += invA * mA.x; oA.y += invA * mA.y;
    oA.z += invA * mA.z; oA.w += invA * mA.w;
    *opA = oA;
    if (hasB) {
        float4 mB = accB;
        #pragma unroll
        for (int t = 0; t < 7; t++) {
            float4 w = sW4[t * 48 + f2];
            mB.x += aeB[t] * w.x; mB.y += aeB[t] * w.y;
            mB.z += aeB[t] * w.z; mB.w += aeB[t] * w.w;
        }
        float4* opB = g_acc1 + node * 48 + f2;
        float4 oB = *opB;
        oB.x += invB * mB.x; oB.y += invB * mB.y;
        oB.z += invB * mB.z; oB.w += invB * mB.w;
        *opB = oB;
    }
}

// ---------------- conv2 node GEMM: elu(acc1) [N,192] @ [192,256] --------------
__global__ void k_gemm2(const float* __restrict__ qw, const float* __restrict__ qb,
                        const float* __restrict__ kw, const float* __restrict__ kb,
                        const float* __restrict__ vw, const float* __restrict__ vb,
                        const float* __restrict__ sw, const float* __restrict__ sb,
                        int n) {
    __shared__ float4 sh[32 * 48];          // elu'd h3 tile [32,192]
    int tid = threadIdx.x;                  // 256 threads
    int arr = tid >> 6, cc = tid & 63;
    const float* W = arr == 0 ? qw : arr == 1 ? kw : arr == 2 ? vw : sw;
    float bias = (arr == 0 ? qb : arr == 1 ? kb : arr == 2 ? vb : sb)[cc];
    int base = blockIdx.x * 32;
    int cnt  = min(32, n - base);
    for (int i = tid; i < cnt * 48; i += 256) {
        float4 v = g_acc1[base * 48 + i];
        v.x = eluf(v.x); v.y = eluf(v.y); v.z = eluf(v.z); v.w = eluf(v.w);
        sh[i] = v;
    }
    __syncthreads();
    float acc[32];
    #pragma unroll
    for (int i = 0; i < 32; i++) acc[i] = bias;
    #pragma unroll 4
    for (int k4 = 0; k4 < 48; k4++) {
        float w0 = W[(4 * k4 + 0) * 64 + cc];
        float w1 = W[(4 * k4 + 1) * 64 + cc];
        float w2 = W[(4 * k4 + 2) * 64 + cc];
        float w3 = W[(4 * k4 + 3) * 64 + cc];
        #pragma unroll
        for (int nn = 0; nn < 32; nn++) {
            float4 h = sh[nn * 48 + k4];
            acc[nn] += h.x * w0 + h.y * w1 + h.z * w2 + h.w * w3;
        }
    }
    for (int nn = 0; nn < cnt; nn++) {
        int node = base + nn;
        if (arr == 0)      ((float*)g_q2)[node * 64 + cc] = acc[nn];
        else if (arr == 1) ((float*)g_kv2)[node * 128 + cc] = acc[nn];
        else if (arr == 2) ((float*)g_kv2)[node * 128 + 64 + cc] = acc[nn];
        else               ((float*)g_acc2)[node * 64 + cc] = acc[nn];
    }
}

// ---------------- conv2: node-centric fused softmax-aggregate -----------------
__global__ void k_conv2(const float* __restrict__ ea, const float* __restrict__ ew, int n) {
    __shared__ float sW[448];               // e2_w [7,64]
    int tid = threadIdx.x;
    for (int i = tid; i < 448; i += 256) sW[i] = ew[i];
    __syncthreads();
    int node = blockIdx.x * 8 + (tid >> 5);
    int lane = tid & 31;
    if (node >= n) return;
    int deg = g_deg[node];
    if (deg == 0) return;
    int rs = g_rowptr[node];

    const float* qr = (const float*)g_q2 + node * 64 + lane * 2;
    float2 qv = *(const float2*)qr;

    float pqh[7];
    #pragma unroll
    for (int t = 0; t < 7; t++) {
        const float* w = &sW[t * 64 + lane * 2];
        float p = qv.x * w[0] + qv.y * w[1];
        p += __shfl_xor_sync(0xffffffffu, p, 1);
        p += __shfl_xor_sync(0xffffffffu, p, 2);
        pqh[t] = p;
    }

    float acc0 = 0.f, acc1 = 0.f, den = 0.f, a0 = 0.f, a1 = 0.f;
    int g = lane & 3;

    int2 se = g_cpack[rs];
    for (int i = 0; i < deg; i++) {
        int s = se.x, eid = se.y;
        if (i + 1 < deg) se = g_cpack[rs + i + 1];
        float eav[7];
        #pragma unroll
        for (int t = 0; t < 7; t++) eav[t] = __ldg(&ea[eid * 7 + t]);
        const float* kv = (const float*)g_kv2 + s * 128 + lane * 2;
        float2 kk = *(const float2*)kv;
        float2 vv = *(const float2*)(kv + 64);
        float lp = qv.x * kk.x + qv.y * kk.y;
        lp += __shfl_xor_sync(0xffffffffu, lp, 1);
        lp += __shfl_xor_sync(0xffffffffu, lp, 2);
        #pragma unroll
        for (int t = 0; t < 7; t++) lp += eav[t] * pqh[t];
        float ex = __expf(lp * 0.35355339059327373f);   // 1/sqrt(8)
        den += ex;
        acc0 += ex * vv.x;
        acc1 += ex * vv.y;
        float elo = g == 0 ? eav[0] : g == 1 ? eav[2] : g == 2 ? eav[4] : eav[6];
        float ehi = g == 0 ? eav[1] : g == 1 ? eav[3] : g == 2 ? eav[5] : 0.f;
        a0 += ex * elo;
        a1 += ex * ehi;
    }

    float inv = 1.f / den;
    int base = lane & ~3;
    float ae[7];
    ae[0] = __shfl_sync(0xffffffffu, a0, base);
    ae[1] = __shfl_sync(0xffffffffu, a1, base);
    ae[2] = __shfl_sync(0xffffffffu, a0, base + 1);
    ae[3] = __shfl_sync(0xffffffffu, a1, base + 1);
    ae[4] = __shfl_sync(0xffffffffu, a0, base + 2);
    ae[5] = __shfl_sync(0xffffffffu, a1, base + 2);
    ae[6] = __shfl_sync(0xffffffffu, a0, base + 3);

    float m0 = acc0, m1 = acc1;
    const float* wb = &sW[lane * 2];
    #pragma unroll
    for (int t = 0; t < 7; t++) {
        m0 += ae[t] * wb[t * 64];
        m1 += ae[t] * wb[t * 64 + 1];
    }
    float* outp = (float*)g_acc2 + node * 64 + lane * 2;
    float2 sk = *(float2*)outp;
    sk.x += m0 * inv;
    sk.y += m1 * inv;
    *(float2*)outp = sk;
}

// ---------------- head: elu -> lin1(64,20) -> elu -> lin2(20,1) --------------
__global__ void k_final(const float* __restrict__ w1, const float* __restrict__ b1,
                        const float* __restrict__ w2, const float* __restrict__ b2,
                        float* __restrict__ out, int n) {
    __shared__ float sw1[64 * 20], sb1[20], sw2[20], sb2v[1];
    int tid = threadIdx.x;
    for (int i = tid; i < 1280; i += 256) sw1[i] = w1[i];
    if (tid < 20) { sb1[tid] = b1[tid]; sw2[tid] = w2[tid]; }
    if (tid == 0) sb2v[0] = b2[0];
    __syncthreads();
    int node = blockIdx.x * 256 + tid;
    if (node >= n) return;
    float h[64];
    const float4* r = g_acc2 + node * 16;
    #pragma unroll
    for (int i = 0; i < 16; i++) {
        float4 v = r[i];
        h[4 * i]     = eluf(v.x);
        h[4 * i + 1] = eluf(v.y);
        h[4 * i + 2] = eluf(v.z);
        h[4 * i + 3] = eluf(v.w);
    }
    float res = sb2v[0];
    #pragma unroll 4
    for (int j = 0; j < 20; j++) {
        float a = sb1[j];
        #pragma unroll
        for (int k = 0; k < 64; k++) a += h[k] * sw1[k * 20 + j];
        res += eluf(a) * sw2[j];
    }
    out[node] = res;
}

// ---------------- host launcher ----------------------------------------------
extern "C" void kernel_launch(void* const* d_in, const int* in_sizes, int n_in,
                              void* d_out, int out_size) {
    const float* x      = (const float*)d_in[0];
    const int*   ei     = (const int*)  d_in[1];
    const float* ea     = (const float*)d_in[2];
    const float* linA_w = (const float*)d_in[3];
    const float* linA_b = (const float*)d_in[4];
    const float* linB_w = (const float*)d_in[5];
    const float* linB_b = (const float*)d_in[6];
    const float* q1_w   = (const float*)d_in[7];
    const float* q1_b   = (const float*)d_in[8];
    const float* k1_w   = (const float*)d_in[9];
    const float* k1_b   = (const float*)d_in[10];
    const float* v1_w   = (const float*)d_in[11];
    const float* v1_b   = (const float*)d_in[12];
    const float* e1_w   = (const float*)d_in[13];
    const float* s1_w   = (const float*)d_in[14];
    const float* s1_b   = (const float*)d_in[15];
    const float* q2_w   = (const float*)d_in[16];
    const float* q2_b   = (const float*)d_in[17];
    const float* k2_w   = (const float*)d_in[18];
    const float* k2_b   = (const float*)d_in[19];
    const float* v2_w   = (const float*)d_in[20];
    const float* v2_b   = (const float*)d_in[21];
    const float* e2_w   = (const float*)d_in[22];
    const float* s2_w   = (const float*)d_in[23];
    const float* s2_b   = (const float*)d_in[24];
    const float* lin1_w = (const float*)d_in[25];
    const float* lin1_b = (const float*)d_in[26];
    const float* lin2_w = (const float*)d_in[27];
    const float* lin2_b = (const float*)d_in[28];

    int n = in_sizes[0] / 23;
    int E = in_sizes[1] / 2;
    const int* src = ei;
    const int* dst = ei + E;
    float* out = (float*)d_out;

    int nb256  = (n + 255) / 256;
    int eb256  = (E + 255) / 256;
    int nbconv = (n + 7) / 8;

    // launch order: h2/gemm1 first (independent of CSR) so the ncu capture
    // window (observed to land ~4th launch) hits a kernel that matters.
    k_zero   <<<nb256, 256>>>(n);
    k_count  <<<eb256, 256>>>(dst, E);
    k_h2     <<<nb256, 256>>>(x, linA_w, linA_b, linB_w, linB_b, n);
    k_gemm1  <<<(n + 127) / 128, 768>>>(q1_w, q1_b, k1_w, k1_b, v1_w, v1_b, s1_w, s1_b, n);
    k_scanA  <<<nb256, 256>>>(n);
    k_scanB  <<<1, 512>>>(nb256);
    k_scanC  <<<nb256, 256>>>(n);
    k_scatter<<<eb256, 256>>>(src, dst, E);
    k_conv1  <<<nbconv, 256>>>(ea, e1_w, n);
    k_gemm2  <<<(n + 31) / 32, 256>>>(q2_w, q2_b, k2_w, k2_b, v2_w, v2_b, s2_w, s2_b, n);
    k_conv2  <<<nbconv, 256>>>(ea, e2_w, n);
    k_final  <<<nb256, 256>>>(lin1_w, lin1_b, lin2_w, lin2_b, out, n);
}

// round 6
// speedup vs baseline: 1.4348x; 1.4348x over previous
#include <cuda_runtime.h>
#include <cuda_bf16.h>
#include <cstdint>

#define NMAX 100000
#define EMAX 800000

typedef unsigned long long ull;

// ---------------- scratch (device globals; no runtime allocation) ------------
__device__ float4 g_h2  [NMAX * 6];    // [N,24] padded (23 + 1 zero)
__device__ float4 g_q1  [NMAX * 48];   // [N,192]
__device__ float4 g_kv1 [NMAX * 96];   // [N,384]: k | v per node
__device__ float4 g_acc1[NMAX * 48];   // skip, then conv1 out (pre-elu)
__device__ float4 g_q2  [NMAX * 16];   // [N,64]
__device__ float4 g_kv2 [NMAX * 32];   // [N,128]: k | v
__device__ float4 g_acc2[NMAX * 16];   // conv2 out (pre-elu)
// CSR scratch
__device__ int  g_deg   [NMAX];
__device__ int  g_part  [NMAX];
__device__ int  g_bsum  [512];
__device__ int  g_rowptr[NMAX];
__device__ int  g_cursor[NMAX];
__device__ int2 g_cpack [EMAX];        // (src, edge_id) grouped by dst

__device__ __forceinline__ float eluf(float x) { return x > 0.f ? x : expm1f(x); }

// ---- f32x2 packed-math helpers ----------------------------------------------
__device__ __forceinline__ ull pk2(float lo, float hi) {
    ull r; asm("mov.b64 %0,{%1,%2};" : "=l"(r) : "f"(lo), "f"(hi)); return r;
}
__device__ __forceinline__ void upk2(ull v, float& lo, float& hi) {
    asm("mov.b64 {%0,%1},%2;" : "=f"(lo), "=f"(hi) : "l"(v));
}
__device__ __forceinline__ ull fma2(ull a, ull b, ull c) {
    ull d; asm("fma.rn.f32x2 %0,%1,%2,%3;" : "=l"(d) : "l"(a), "l"(b), "l"(c)); return d;
}
__device__ __forceinline__ void lds_v2u64(ull& a, ull& b, uint32_t addr) {
    asm volatile("ld.shared.v2.u64 {%0,%1},[%2];" : "=l"(a), "=l"(b) : "r"(addr));
}
__device__ __forceinline__ ull lds_u64(uint32_t addr) {
    ull a; asm volatile("ld.shared.b64 %0,[%1];" : "=l"(a) : "r"(addr)); return a;
}
__device__ __forceinline__ uint32_t smem_u32(const void* p) {
    uint32_t a;
    asm("{ .reg .u64 t; cvta.to.shared.u64 t, %1; cvt.u32.u64 %0, t; }" : "=r"(a) : "l"(p));
    return a;
}

// ---------------- CSR build ---------------------------------------------------
__global__ void k_zero(int n) {
    int i = blockIdx.x * blockDim.x + threadIdx.x;
    if (i < n) g_deg[i] = 0;
}
__global__ void k_count(const int* __restrict__ dst, int E) {
    int e = blockIdx.x * blockDim.x + threadIdx.x;
    if (e < E) atomicAdd(&g_deg[dst[e]], 1);
}
__global__ void k_scanA(int n) {                 // 256 threads/block
    __shared__ int s[256];
    int tid = threadIdx.x, i = blockIdx.x * 256 + tid;
    int v = (i < n) ? g_deg[i] : 0;
    s[tid] = v; __syncthreads();
    #pragma unroll
    for (int off = 1; off < 256; off <<= 1) {
        int t = (tid >= off) ? s[tid - off] : 0;
        __syncthreads();
        s[tid] += t;
        __syncthreads();
    }
    if (i < n) g_part[i] = s[tid] - v;           // exclusive within block
    if (tid == 255) g_bsum[blockIdx.x] = s[255];
}
__global__ void k_scanB(int nb) {                // single block, 512 threads
    __shared__ int s[512];
    int tid = threadIdx.x;
    int v = (tid < nb) ? g_bsum[tid] : 0;
    s[tid] = v; __syncthreads();
    #pragma unroll
    for (int off = 1; off < 512; off <<= 1) {
        int t = (tid >= off) ? s[tid - off] : 0;
        __syncthreads();
        s[tid] += t;
        __syncthreads();
    }
    g_bsum[tid] = s[tid] - v;                    // exclusive block offsets
}
__global__ void k_scanC(int n) {
    int i = blockIdx.x * blockDim.x + threadIdx.x;
    if (i < n) {
        int r = g_part[i] + g_bsum[i >> 8];
        g_rowptr[i] = r;
        g_cursor[i] = r;
    }
}
__global__ void k_scatter(const int* __restrict__ src, const int* __restrict__ dst, int E) {
    int e = blockIdx.x * blockDim.x + threadIdx.x;
    if (e < E) {
        int d = dst[e];
        int pos = atomicAdd(&g_cursor[d], 1);
        g_cpack[pos] = make_int2(src[e], e);
    }
}

// ---------------- h2 = elu(elu(x@A+bA)@B+bB), padded to 24 -------------------
__global__ void k_h2(const float* __restrict__ x,
                     const float* __restrict__ Aw, const float* __restrict__ Ab,
                     const float* __restrict__ Bw, const float* __restrict__ Bb,
                     int n) {
    __shared__ float sA[23 * 23], sB[23 * 23], sbA[23], sbB[23];
    __shared__ float sx[256 * 23];
    int tid = threadIdx.x;
    for (int i = tid; i < 23 * 23; i += 256) { sA[i] = Aw[i]; sB[i] = Bw[i]; }
    if (tid < 23) { sbA[tid] = Ab[tid]; sbB[tid] = Bb[tid]; }
    int base = blockIdx.x * 256;
    int cnt  = min(256, n - base);
    for (int i = tid; i < cnt * 23; i += 256) sx[i] = x[base * 23 + i];
    __syncthreads();
    if (tid < cnt) {
        const float* xr = &sx[tid * 23];
        float h1[23];
        #pragma unroll
        for (int j = 0; j < 23; j++) {
            float a = sbA[j];
            #pragma unroll
            for (int k = 0; k < 23; k++) a += xr[k] * sA[k * 23 + j];
            h1[j] = eluf(a);
        }
        float* out = (float*)g_h2 + (base + tid) * 24;
        #pragma unroll
        for (int j = 0; j < 23; j++) {
            float a = sbB[j];
            #pragma unroll
            for (int k = 0; k < 23; k++) a += h1[k] * sB[k * 23 + j];
            out[j] = eluf(a);
        }
        out[23] = 0.f;
    }
}

// ---------------- conv1 node GEMM: [N,24]@[24,768], f32x2 --------------------
__global__ __launch_bounds__(768) void k_gemm1(
        const float* __restrict__ qw, const float* __restrict__ qb,
        const float* __restrict__ kw, const float* __restrict__ kb,
        const float* __restrict__ vw, const float* __restrict__ vb,
        const float* __restrict__ sw, const float* __restrict__ sb,
        int n) {
    __shared__ float sT[24 * 128];          // transposed [k][node]
    int tid = threadIdx.x;                  // 768 threads
    int base = blockIdx.x * 128;
    int cnt  = min(128, n - base);
    {
        int nn = tid & 127, k4 = tid >> 7;  // k4 in 0..5
        float4 v = (nn < cnt) ? g_h2[(base + nn) * 6 + k4] : make_float4(0, 0, 0, 0);
        sT[(4 * k4 + 0) * 128 + nn] = v.x;
        sT[(4 * k4 + 1) * 128 + nn] = v.y;
        sT[(4 * k4 + 2) * 128 + nn] = v.z;
        sT[(4 * k4 + 3) * 128 + nn] = v.w;
    }
    __syncthreads();
    int arr = tid / 192, cc = tid % 192;
    const float* W = arr == 0 ? qw : arr == 1 ? kw : arr == 2 ? vw : sw;
    const float* B = arr == 0 ? qb : arr == 1 ? kb : arr == 2 ? vb : sb;
    float* op; int stride; int coff = cc;
    if (arr == 0)      { op = (float*)g_q1;  stride = 192; }
    else if (arr == 1) { op = (float*)g_kv1; stride = 384; }
    else if (arr == 2) { op = (float*)g_kv1; stride = 384; coff = 192 + cc; }
    else               { op = (float*)g_acc1; stride = 192; }
    float w[23];
    #pragma unroll
    for (int k = 0; k < 23; k++) w[k] = W[k * 192 + cc];
    float bias = B[cc];
    uint32_t sbase = smem_u32(sT);
    for (int ch = 0; ch < 8; ch++) {
        int n0 = ch * 16;
        ull acc[8];
        ull b2 = pk2(bias, bias);
        #pragma unroll
        for (int p = 0; p < 8; p++) acc[p] = b2;
        #pragma unroll
        for (int k = 0; k < 23; k++) {
            ull w2 = pk2(w[k], w[k]);
            uint32_t ra = sbase + (uint32_t)(k * 128 + n0) * 4u;
            #pragma unroll
            for (int p = 0; p < 4; p++) {
                ull h01, h23;
                lds_v2u64(h01, h23, ra + 16u * p);
                acc[2 * p]     = fma2(h01, w2, acc[2 * p]);
                acc[2 * p + 1] = fma2(h23, w2, acc[2 * p + 1]);
            }
        }
        #pragma unroll
        for (int p = 0; p < 8; p++) {
            float lo, hi; upk2(acc[p], lo, hi);
            int na = n0 + 2 * p, nb = na + 1;
            if (na < cnt) op[(size_t)(base + na) * stride + coff] = lo;
            if (nb < cnt) op[(size_t)(base + nb) * stride + coff] = hi;
        }
    }
}

// ---------------- conv1: node-centric fused softmax-aggregate (R2 proven) ----
__global__ void k_conv1(const float* __restrict__ ea, const float* __restrict__ ew, int n) {
    __shared__ float sW[1344];              // e1_w [7,192]
    int tid = threadIdx.x;
    for (int i = tid; i < 1344; i += 256) sW[i] = ew[i];
    __syncthreads();
    int node = blockIdx.x * 8 + (tid >> 5);
    int lane = tid & 31;
    if (node >= n) return;
    int deg = g_deg[node];
    if (deg == 0) return;                   // acc1 already holds skip
    int rs = g_rowptr[node];

    const float* qr = (const float*)g_q1 + node * 192 + lane * 6;
    float q0, q1, q2, q3, q4, q5;
    { float2 a = *(const float2*)qr;       q0 = a.x; q1 = a.y;
      float2 b = *(const float2*)(qr + 2); q2 = b.x; q3 = b.y;
      float2 c = *(const float2*)(qr + 4); q4 = c.x; q5 = c.y; }

    float pqh[7];
    #pragma unroll
    for (int t = 0; t < 7; t++) {
        const float* w = &sW[t * 192 + lane * 6];
        float p = q0 * w[0] + q1 * w[1] + q2 * w[2] + q3 * w[3] + q4 * w[4] + q5 * w[5];
        p += __shfl_xor_sync(0xffffffffu, p, 1);
        p += __shfl_xor_sync(0xffffffffu, p, 2);
        pqh[t] = p;
    }

    float acc0 = 0.f, acc1 = 0.f, acc2 = 0.f, acc3 = 0.f, acc4 = 0.f, acc5 = 0.f;
    float den = 0.f, a0 = 0.f, a1 = 0.f;
    int g = lane & 3;

    int2 se = g_cpack[rs];
    for (int i = 0; i < deg; i++) {
        int s = se.x, eid = se.y;
        if (i + 1 < deg) se = g_cpack[rs + i + 1];
        float eav[7];
        #pragma unroll
        for (int t = 0; t < 7; t++) eav[t] = __ldg(&ea[eid * 7 + t]);
        const float* kv = (const float*)g_kv1 + s * 384 + lane * 6;
        float k0, k1, k2, k3, k4, k5, v0, v1, v2, v3, v4, v5;
        { float2 a = *(const float2*)kv;         k0 = a.x; k1 = a.y;
          float2 b = *(const float2*)(kv + 2);   k2 = b.x; k3 = b.y;
          float2 c = *(const float2*)(kv + 4);   k4 = c.x; k5 = c.y;
          float2 p = *(const float2*)(kv + 192); v0 = p.x; v1 = p.y;
          float2 r = *(const float2*)(kv + 194); v2 = r.x; v3 = r.y;
          float2 u = *(const float2*)(kv + 196); v4 = u.x; v5 = u.y; }
        float lp = q0 * k0 + q1 * k1 + q2 * k2 + q3 * k3 + q4 * k4 + q5 * k5;
        lp += __shfl_xor_sync(0xffffffffu, lp, 1);
        lp += __shfl_xor_sync(0xffffffffu, lp, 2);
        #pragma unroll
        for (int t = 0; t < 7; t++) lp += eav[t] * pqh[t];
        float ex = __expf(lp * 0.20412414523193154f);   // 1/sqrt(24)
        den += ex;
        acc0 += ex * v0; acc1 += ex * v1; acc2 += ex * v2;
        acc3 += ex * v3; acc4 += ex * v4; acc5 += ex * v5;
        float elo = g == 0 ? eav[0] : g == 1 ? eav[2] : g == 2 ? eav[4] : eav[6];
        float ehi = g == 0 ? eav[1] : g == 1 ? eav[3] : g == 2 ? eav[5] : 0.f;
        a0 += ex * elo;
        a1 += ex * ehi;
    }

    float inv = 1.f / den;
    int base = lane & ~3;
    float ae[7];
    ae[0] = __shfl_sync(0xffffffffu, a0, base);
    ae[1] = __shfl_sync(0xffffffffu, a1, base);
    ae[2] = __shfl_sync(0xffffffffu, a0, base + 1);
    ae[3] = __shfl_sync(0xffffffffu, a1, base + 1);
    ae[4] = __shfl_sync(0xffffffffu, a0, base + 2);
    ae[5] = __shfl_sync(0xffffffffu, a1, base + 2);
    ae[6] = __shfl_sync(0xffffffffu, a0, base + 3);

    float m[6] = {acc0, acc1, acc2, acc3, acc4, acc5};
    const float* wb = &sW[lane * 6];
    #pragma unroll
    for (int j = 0; j < 6; j++) {
        #pragma unroll
        for (int t = 0; t < 7; t++) m[j] += ae[t] * wb[t * 192 + j];
    }
    float* outp = (float*)g_acc1 + node * 192 + lane * 6;
    #pragma unroll
    for (int j2 = 0; j2 < 3; j2++) {
        float2 sk = *(float2*)(outp + 2 * j2);
        sk.x += m[2 * j2] * inv;
        sk.y += m[2 * j2 + 1] * inv;
        *(float2*)(outp + 2 * j2) = sk;
    }
}

// ---------------- conv2 node GEMM: elu(acc1) [N,192]@[192,256], f32x2 --------
__global__ __launch_bounds__(256) void k_gemm2(
        const float* __restrict__ qw, const float* __restrict__ qb,
        const float* __restrict__ kw, const float* __restrict__ kb,
        const float* __restrict__ vw, const float* __restrict__ vb,
        const float* __restrict__ sw, const float* __restrict__ sb,
        int n) {
    __shared__ float sT[192 * 36];          // transposed [k][node], pad 36
    int tid = threadIdx.x;                  // 256 threads
    int base = blockIdx.x * 32;
    int cnt  = min(32, n - base);
    {
        int nn = tid & 31, kq = tid >> 5;   // kq 0..7
        #pragma unroll
        for (int j = 0; j < 6; j++) {
            int k4 = kq + 8 * j;
            float4 v = (nn < cnt) ? g_acc1[(base + nn) * 48 + k4] : make_float4(0, 0, 0, 0);
            v.x = eluf(v.x); v.y = eluf(v.y); v.z = eluf(v.z); v.w = eluf(v.w);
            sT[(4 * k4 + 0) * 36 + nn] = v.x;
            sT[(4 * k4 + 1) * 36 + nn] = v.y;
            sT[(4 * k4 + 2) * 36 + nn] = v.z;
            sT[(4 * k4 + 3) * 36 + nn] = v.w;
        }
    }
    __syncthreads();
    int arr = tid >> 6, cc = tid & 63;
    const float* W = arr == 0 ? qw : arr == 1 ? kw : arr == 2 ? vw : sw;
    float bias = (arr == 0 ? qb : arr == 1 ? kb : arr == 2 ? vb : sb)[cc];
    float* op; int stride; int coff = cc;
    if (arr == 0)      { op = (float*)g_q2;  stride = 64; }
    else if (arr == 1) { op = (float*)g_kv2; stride = 128; }
    else if (arr == 2) { op = (float*)g_kv2; stride = 128; coff = 64 + cc; }
    else               { op = (float*)g_acc2; stride = 64; }
    ull acc[16];
    ull b2 = pk2(bias, bias);
    #pragma unroll
    for (int p = 0; p < 16; p++) acc[p] = b2;
    uint32_t sbase = smem_u32(sT);
    #pragma unroll 2
    for (int k = 0; k < 192; k++) {
        float w = W[k * 64 + cc];
        ull w2 = pk2(w, w);
        uint32_t ra = sbase + (uint32_t)(k * 36) * 4u;
        #pragma unroll
        for (int p = 0; p < 8; p++) {
            ull h01, h23;
            lds_v2u64(h01, h23, ra + 16u * p);
            acc[2 * p]     = fma2(h01, w2, acc[2 * p]);
            acc[2 * p + 1] = fma2(h23, w2, acc[2 * p + 1]);
        }
    }
    #pragma unroll
    for (int p = 0; p < 16; p++) {
        float lo, hi; upk2(acc[p], lo, hi);
        int na = 2 * p, nb = na + 1;
        if (na < cnt) op[(size_t)(base + na) * stride + coff] = lo;
        if (nb < cnt) op[(size_t)(base + nb) * stride + coff] = hi;
    }
}

// ---------------- conv2: node-centric fused softmax-aggregate (R2 proven) ----
__global__ void k_conv2(const float* __restrict__ ea, const float* __restrict__ ew, int n) {
    __shared__ float sW[448];               // e2_w [7,64]
    int tid = threadIdx.x;
    for (int i = tid; i < 448; i += 256) sW[i] = ew[i];
    __syncthreads();
    int node = blockIdx.x * 8 + (tid >> 5);
    int lane = tid & 31;
    if (node >= n) return;
    int deg = g_deg[node];
    if (deg == 0) return;
    int rs = g_rowptr[node];

    const float* qr = (const float*)g_q2 + node * 64 + lane * 2;
    float2 qv = *(const float2*)qr;

    float pqh[7];
    #pragma unroll
    for (int t = 0; t < 7; t++) {
        const float* w = &sW[t * 64 + lane * 2];
        float p = qv.x * w[0] + qv.y * w[1];
        p += __shfl_xor_sync(0xffffffffu, p, 1);
        p += __shfl_xor_sync(0xffffffffu, p, 2);
        pqh[t] = p;
    }

    float acc0 = 0.f, acc1 = 0.f, den = 0.f, a0 = 0.f, a1 = 0.f;
    int g = lane & 3;

    int2 se = g_cpack[rs];
    for (int i = 0; i < deg; i++) {
        int s = se.x, eid = se.y;
        if (i + 1 < deg) se = g_cpack[rs + i + 1];
        float eav[7];
        #pragma unroll
        for (int t = 0; t < 7; t++) eav[t] = __ldg(&ea[eid * 7 + t]);
        const float* kv = (const float*)g_kv2 + s * 128 + lane * 2;
        float2 kk = *(const float2*)kv;
        float2 vv = *(const float2*)(kv + 64);
        float lp = qv.x * kk.x + qv.y * kk.y;
        lp += __shfl_xor_sync(0xffffffffu, lp, 1);
        lp += __shfl_xor_sync(0xffffffffu, lp, 2);
        #pragma unroll
        for (int t = 0; t < 7; t++) lp += eav[t] * pqh[t];
        float ex = __expf(lp * 0.35355339059327373f);   // 1/sqrt(8)
        den += ex;
        acc0 += ex * vv.x;
        acc1 += ex * vv.y;
        float elo = g == 0 ? eav[0] : g == 1 ? eav[2] : g == 2 ? eav[4] : eav[6];
        float ehi = g == 0 ? eav[1] : g == 1 ? eav[3] : g == 2 ? eav[5] : 0.f;
        a0 += ex * elo;
        a1 += ex * ehi;
    }

    float inv = 1.f / den;
    int base = lane & ~3;
    float ae[7];
    ae[0] = __shfl_sync(0xffffffffu, a0, base);
    ae[1] = __shfl_sync(0xffffffffu, a1, base);
    ae[2] = __shfl_sync(0xffffffffu, a0, base + 1);
    ae[3] = __shfl_sync(0xffffffffu, a1, base + 1);
    ae[4] = __shfl_sync(0xffffffffu, a0, base + 2);
    ae[5] = __shfl_sync(0xffffffffu, a1, base + 2);
    ae[6] = __shfl_sync(0xffffffffu, a0, base + 3);

    float m0 = acc0, m1 = acc1;
    const float* wb = &sW[lane * 2];
    #pragma unroll
    for (int t = 0; t < 7; t++) {
        m0 += ae[t] * wb[t * 64];
        m1 += ae[t] * wb[t * 64 + 1];
    }
    float* outp = (float*)g_acc2 + node * 64 + lane * 2;
    float2 sk = *(float2*)outp;
    sk.x += m0 * inv;
    sk.y += m1 * inv;
    *(float2*)outp = sk;
}

// ---------------- head: elu -> lin1(64,20) -> elu -> lin2(20,1), f32x2 -------
__global__ void k_final(const float* __restrict__ w1, const float* __restrict__ b1,
                        const float* __restrict__ w2, const float* __restrict__ b2,
                        float* __restrict__ out, int n) {
    __shared__ float sw1t[20 * 64];         // transposed [j][k]
    __shared__ float sb1[20], sw2[20], sb2v[1];
    int tid = threadIdx.x;
    for (int i = tid; i < 1280; i += 256) {
        int k = i / 20, j = i % 20;
        sw1t[j * 64 + k] = w1[i];
    }
    if (tid < 20) { sb1[tid] = b1[tid]; sw2[tid] = w2[tid]; }
    if (tid == 0) sb2v[0] = b2[0];
    __syncthreads();
    int node = blockIdx.x * 256 + tid;
    if (node >= n) return;
    ull hp[32];
    const float4* r = g_acc2 + node * 16;
    #pragma unroll
    for (int i = 0; i < 16; i++) {
        float4 v = r[i];
        hp[2 * i]     = pk2(eluf(v.x), eluf(v.y));
        hp[2 * i + 1] = pk2(eluf(v.z), eluf(v.w));
    }
    uint32_t sbase = smem_u32(sw1t);
    float res = sb2v[0];
    #pragma unroll 2
    for (int j = 0; j < 20; j++) {
        ull a2 = 0;
        uint32_t ra = sbase + (uint32_t)j * 256u;
        #pragma unroll
        for (int kk = 0; kk < 32; kk++) {
            ull w2p = lds_u64(ra + 8u * kk);
            a2 = fma2(hp[kk], w2p, a2);
        }
        float lo, hi; upk2(a2, lo, hi);
        res += eluf(sb1[j] + lo + hi) * sw2[j];
    }
    out[node] = res;
}

// ---------------- host launcher ----------------------------------------------
extern "C" void kernel_launch(void* const* d_in, const int* in_sizes, int n_in,
                              void* d_out, int out_size) {
    const float* x      = (const float*)d_in[0];
    const int*   ei     = (const int*)  d_in[1];
    const float* ea     = (const float*)d_in[2];
    const float* linA_w = (const float*)d_in[3];
    const float* linA_b = (const float*)d_in[4];
    const float* linB_w = (const float*)d_in[5];
    const float* linB_b = (const float*)d_in[6];
    const float* q1_w   = (const float*)d_in[7];
    const float* q1_b   = (const float*)d_in[8];
    const float* k1_w   = (const float*)d_in[9];
    const float* k1_b   = (const float*)d_in[10];
    const float* v1_w   = (const float*)d_in[11];
    const float* v1_b   = (const float*)d_in[12];
    const float* e1_w   = (const float*)d_in[13];
    const float* s1_w   = (const float*)d_in[14];
    const float* s1_b   = (const float*)d_in[15];
    const float* q2_w   = (const float*)d_in[16];
    const float* q2_b   = (const float*)d_in[17];
    const float* k2_w   = (const float*)d_in[18];
    const float* k2_b   = (const float*)d_in[19];
    const float* v2_w   = (const float*)d_in[20];
    const float* v2_b   = (const float*)d_in[21];
    const float* e2_w   = (const float*)d_in[22];
    const float* s2_w   = (const float*)d_in[23];
    const float* s2_b   = (const float*)d_in[24];
    const float* lin1_w = (const float*)d_in[25];
    const float* lin1_b = (const float*)d_in[26];
    const float* lin2_w = (const float*)d_in[27];
    const float* lin2_b = (const float*)d_in[28];

    int n = in_sizes[0] / 23;
    int E = in_sizes[1] / 2;
    const int* src = ei;
    const int* dst = ei + E;
    float* out = (float*)d_out;

    int nb256  = (n + 255) / 256;
    int eb256  = (E + 255) / 256;
    int nbconv = (n + 7) / 8;

    // launch order: h2/gemm1 early so the ncu capture slot (4th launch) hits
    // k_gemm1 again for a direct f32x2 predict-verify.
    k_zero   <<<nb256, 256>>>(n);
    k_count  <<<eb256, 256>>>(dst, E);
    k_h2     <<<nb256, 256>>>(x, linA_w, linA_b, linB_w, linB_b, n);
    k_gemm1  <<<(n + 127) / 128, 768>>>(q1_w, q1_b, k1_w, k1_b, v1_w, v1_b, s1_w, s1_b, n);
    k_scanA  <<<nb256, 256>>>(n);
    k_scanB  <<<1, 512>>>(nb256);
    k_scanC  <<<nb256, 256>>>(n);
    k_scatter<<<eb256, 256>>>(src, dst, E);
    k_conv1  <<<nbconv, 256>>>(ea, e1_w, n);
    k_gemm2  <<<(n + 31) / 32, 256>>>(q2_w, q2_b, k2_w, k2_b, v2_w, v2_b, s2_w, s2_b, n);
    k_conv2  <<<nbconv, 256>>>(ea, e2_w, n);
    k_final  <<<nb256, 256>>>(lin1_w, lin1_b, lin2_w, lin2_b, out, n);
}

// round 7
// speedup vs baseline: 1.4618x; 1.0188x over previous
#include <cuda_runtime.h>
#include <cuda_bf16.h>
#include <cstdint>

#define NMAX 100000
#define EMAX 800000

typedef unsigned long long ull;

// ---------------- scratch (device globals; no runtime allocation) ------------
__device__ float4 g_h2  [NMAX * 6];    // [N,24] padded (23 + 1 zero)
__device__ float4 g_q1  [NMAX * 48];   // [N,192]  PERMUTED channel layout
__device__ float4 g_kv1 [NMAX * 96];   // [N,384]: k | v per node, PERMUTED
__device__ float4 g_acc1[NMAX * 48];   // skip, then conv1 out (pre-elu), TRUE order
__device__ float4 g_q2  [NMAX * 16];   // [N,64]
__device__ float4 g_kv2 [NMAX * 32];   // [N,128]: k | v
__device__ float4 g_acc2[NMAX * 16];   // conv2 out (pre-elu)
// CSR scratch
__device__ int  g_deg   [NMAX];
__device__ int  g_part  [NMAX];
__device__ int  g_bsum  [512];
__device__ int  g_rowptr[NMAX];
__device__ int  g_cursor[NMAX];
__device__ int2 g_cpack [EMAX];        // (src, edge_id) grouped by dst

__device__ __forceinline__ float eluf(float x) { return x > 0.f ? x : expm1f(x); }

// ---- f32x2 packed-math helpers ----------------------------------------------
__device__ __forceinline__ ull pk2(float lo, float hi) {
    ull r; asm("mov.b64 %0,{%1,%2};" : "=l"(r) : "f"(lo), "f"(hi)); return r;
}
__device__ __forceinline__ void upk2(ull v, float& lo, float& hi) {
    asm("mov.b64 {%0,%1},%2;" : "=f"(lo), "=f"(hi) : "l"(v));
}
__device__ __forceinline__ ull fma2(ull a, ull b, ull c) {
    ull d; asm("fma.rn.f32x2 %0,%1,%2,%3;" : "=l"(d) : "l"(a), "l"(b), "l"(c)); return d;
}
__device__ __forceinline__ void lds_v2u64(ull& a, ull& b, uint32_t addr) {
    asm volatile("ld.shared.v2.u64 {%0,%1},[%2];" : "=l"(a), "=l"(b) : "r"(addr));
}
__device__ __forceinline__ ull lds_u64(uint32_t addr) {
    ull a; asm volatile("ld.shared.b64 %0,[%1];" : "=l"(a) : "r"(addr)); return a;
}
__device__ __forceinline__ uint32_t smem_u32(const void* p) {
    uint32_t a;
    asm("{ .reg .u64 t; cvta.to.shared.u64 t, %1; cvt.u32.u64 %0, t; }" : "=r"(a) : "l"(p));
    return a;
}

// ---------------- CSR build ---------------------------------------------------
__global__ void k_zero(int n) {
    int i = blockIdx.x * blockDim.x + threadIdx.x;
    if (i < n) g_deg[i] = 0;
}
__global__ void k_count(const int* __restrict__ dst, int E) {
    int e = blockIdx.x * blockDim.x + threadIdx.x;
    if (e < E) atomicAdd(&g_deg[dst[e]], 1);
}
__global__ void k_scanA(int n) {                 // 256 threads/block
    __shared__ int s[256];
    int tid = threadIdx.x, i = blockIdx.x * 256 + tid;
    int v = (i < n) ? g_deg[i] : 0;
    s[tid] = v; __syncthreads();
    #pragma unroll
    for (int off = 1; off < 256; off <<= 1) {
        int t = (tid >= off) ? s[tid - off] : 0;
        __syncthreads();
        s[tid] += t;
        __syncthreads();
    }
    if (i < n) g_part[i] = s[tid] - v;           // exclusive within block
    if (tid == 255) g_bsum[blockIdx.x] = s[255];
}
__global__ void k_scanB(int nb) {                // single block, 512 threads
    __shared__ int s[512];
    int tid = threadIdx.x;
    int v = (tid < nb) ? g_bsum[tid] : 0;
    s[tid] = v; __syncthreads();
    #pragma unroll
    for (int off = 1; off < 512; off <<= 1) {
        int t = (tid >= off) ? s[tid - off] : 0;
        __syncthreads();
        s[tid] += t;
        __syncthreads();
    }
    g_bsum[tid] = s[tid] - v;                    // exclusive block offsets
}
__global__ void k_scanC(int n) {
    int i = blockIdx.x * blockDim.x + threadIdx.x;
    if (i < n) {
        int r = g_part[i] + g_bsum[i >> 8];
        g_rowptr[i] = r;
        g_cursor[i] = r;
    }
}
__global__ void k_scatter(const int* __restrict__ src, const int* __restrict__ dst, int E) {
    int e = blockIdx.x * blockDim.x + threadIdx.x;
    if (e < E) {
        int d = dst[e];
        int pos = atomicAdd(&g_cursor[d], 1);
        g_cpack[pos] = make_int2(src[e], e);
    }
}

// ---------------- h2 = elu(elu(x@A+bA)@B+bB), padded to 24 -------------------
__global__ void k_h2(const float* __restrict__ x,
                     const float* __restrict__ Aw, const float* __restrict__ Ab,
                     const float* __restrict__ Bw, const float* __restrict__ Bb,
                     int n) {
    __shared__ float sA[23 * 23], sB[23 * 23], sbA[23], sbB[23];
    __shared__ float sx[256 * 23];
    int tid = threadIdx.x;
    for (int i = tid; i < 23 * 23; i += 256) { sA[i] = Aw[i]; sB[i] = Bw[i]; }
    if (tid < 23) { sbA[tid] = Ab[tid]; sbB[tid] = Bb[tid]; }
    int base = blockIdx.x * 256;
    int cnt  = min(256, n - base);
    for (int i = tid; i < cnt * 23; i += 256) sx[i] = x[base * 23 + i];
    __syncthreads();
    if (tid < cnt) {
        const float* xr = &sx[tid * 23];
        float h1[23];
        #pragma unroll
        for (int j = 0; j < 23; j++) {
            float a = sbA[j];
            #pragma unroll
            for (int k = 0; k < 23; k++) a += xr[k] * sA[k * 23 + j];
            h1[j] = eluf(a);
        }
        float* out = (float*)g_h2 + (base + tid) * 24;
        #pragma unroll
        for (int j = 0; j < 23; j++) {
            float a = sbB[j];
            #pragma unroll
            for (int k = 0; k < 23; k++) a += h1[k] * sB[k * 23 + j];
            out[j] = eluf(a);
        }
        out[23] = 0.f;
    }
}

// ---------------- conv1 node GEMM: [N,24]@[24,768], f32x2, permuted qkv ------
// storage position p (0..191) of q/k/v holds TRUE channel
//   cc(p) = ((p&31)>>2)*24 + (p&3)*6 + (p>>5)
// so that conv1's lane l reads positions {l+32j} = one head's 6 channels,
// fully coalesced. Skip (arr==3) stays identity (feeds gemm2 linearly).
__global__ __launch_bounds__(768) void k_gemm1(
        const float* __restrict__ qw, const float* __restrict__ qb,
        const float* __restrict__ kw, const float* __restrict__ kb,
        const float* __restrict__ vw, const float* __restrict__ vb,
        const float* __restrict__ sw, const float* __restrict__ sb,
        int n) {
    __shared__ float sT[24 * 128];          // transposed [k][node]
    int tid = threadIdx.x;                  // 768 threads
    int base = blockIdx.x * 128;
    int cnt  = min(128, n - base);
    {
        int nn = tid & 127, k4 = tid >> 7;  // k4 in 0..5
        float4 v = (nn < cnt) ? g_h2[(base + nn) * 6 + k4] : make_float4(0, 0, 0, 0);
        sT[(4 * k4 + 0) * 128 + nn] = v.x;
        sT[(4 * k4 + 1) * 128 + nn] = v.y;
        sT[(4 * k4 + 2) * 128 + nn] = v.z;
        sT[(4 * k4 + 3) * 128 + nn] = v.w;
    }
    __syncthreads();
    int arr = tid / 192, p = tid % 192;
    int cc = (arr <= 2) ? (((p & 31) >> 2) * 24 + (p & 3) * 6 + (p >> 5)) : p;
    const float* W = arr == 0 ? qw : arr == 1 ? kw : arr == 2 ? vw : sw;
    const float* B = arr == 0 ? qb : arr == 1 ? kb : arr == 2 ? vb : sb;
    float* op; int stride; int coff = p;
    if (arr == 0)      { op = (float*)g_q1;  stride = 192; }
    else if (arr == 1) { op = (float*)g_kv1; stride = 384; }
    else if (arr == 2) { op = (float*)g_kv1; stride = 384; coff = 192 + p; }
    else               { op = (float*)g_acc1; stride = 192; }
    float w[23];
    #pragma unroll
    for (int k = 0; k < 23; k++) w[k] = W[k * 192 + cc];
    float bias = B[cc];
    uint32_t sbase = smem_u32(sT);
    for (int ch = 0; ch < 8; ch++) {
        int n0 = ch * 16;
        ull acc[8];
        ull b2 = pk2(bias, bias);
        #pragma unroll
        for (int q8 = 0; q8 < 8; q8++) acc[q8] = b2;
        #pragma unroll
        for (int k = 0; k < 23; k++) {
            ull w2 = pk2(w[k], w[k]);
            uint32_t ra = sbase + (uint32_t)(k * 128 + n0) * 4u;
            #pragma unroll
            for (int q4 = 0; q4 < 4; q4++) {
                ull h01, h23;
                lds_v2u64(h01, h23, ra + 16u * q4);
                acc[2 * q4]     = fma2(h01, w2, acc[2 * q4]);
                acc[2 * q4 + 1] = fma2(h23, w2, acc[2 * q4 + 1]);
            }
        }
        #pragma unroll
        for (int q8 = 0; q8 < 8; q8++) {
            float lo, hi; upk2(acc[q8], lo, hi);
            int na = n0 + 2 * q8, nb = na + 1;
            if (na < cnt) op[(size_t)(base + na) * stride + coff] = lo;
            if (nb < cnt) op[(size_t)(base + nb) * stride + coff] = hi;
        }
    }
}

// ---------------- conv1: node-centric fused softmax-aggregate -----------------
// Permuted q/k/v layout: lane l reads positions {l + 32j}, j=0..5 — every
// global load is one fully-coalesced 128B line. True channel of (l,j) is
// tc+j with tc = (l/4)*24 + (l&3)*6 (used for sW and acc1, which stay in
// true-channel order).
__global__ void k_conv1(const float* __restrict__ ea, const float* __restrict__ ew, int n) {
    __shared__ float sW[1344];              // e1_w [7,192] true order
    int tid = threadIdx.x;
    for (int i = tid; i < 1344; i += 256) sW[i] = ew[i];
    __syncthreads();
    int node = blockIdx.x * 8 + (tid >> 5);
    int lane = tid & 31;
    if (node >= n) return;
    int deg = g_deg[node];
    if (deg == 0) return;                   // acc1 already holds skip
    int rs = g_rowptr[node];
    int g = lane & 3;
    int tc = (lane >> 2) * 24 + g * 6;      // true channel base (<= 186)

    const float* qf = (const float*)g_q1 + node * 192 + lane;
    float q0 = qf[0],  q1 = qf[32],  q2 = qf[64],
          q3 = qf[96], q4 = qf[128], q5 = qf[160];

    float pqh[7];
    #pragma unroll
    for (int t = 0; t < 7; t++) {
        const float* w = &sW[t * 192 + tc];
        float p = q0 * w[0] + q1 * w[1] + q2 * w[2] + q3 * w[3] + q4 * w[4] + q5 * w[5];
        p += __shfl_xor_sync(0xffffffffu, p, 1);
        p += __shfl_xor_sync(0xffffffffu, p, 2);
        pqh[t] = p;
    }

    float acc0 = 0.f, acc1 = 0.f, acc2 = 0.f, acc3 = 0.f, acc4 = 0.f, acc5 = 0.f;
    float den = 0.f, a0 = 0.f, a1 = 0.f;

    int2 se = g_cpack[rs];
    for (int i = 0; i < deg; i++) {
        int s = se.x, eid = se.y;
        if (i + 1 < deg) se = g_cpack[rs + i + 1];
        float eav[7];
        #pragma unroll
        for (int t = 0; t < 7; t++) eav[t] = __ldg(&ea[eid * 7 + t]);
        const float* kf = (const float*)g_kv1 + s * 384 + lane;
        float k0 = kf[0],   k1 = kf[32],  k2 = kf[64],
              k3 = kf[96],  k4 = kf[128], k5 = kf[160];
        float v0 = kf[192], v1 = kf[224], v2 = kf[256],
              v3 = kf[288], v4 = kf[320], v5 = kf[352];
        float lp = q0 * k0 + q1 * k1 + q2 * k2 + q3 * k3 + q4 * k4 + q5 * k5;
        lp += __shfl_xor_sync(0xffffffffu, lp, 1);
        lp += __shfl_xor_sync(0xffffffffu, lp, 2);
        #pragma unroll
        for (int t = 0; t < 7; t++) lp += eav[t] * pqh[t];
        float ex = __expf(lp * 0.20412414523193154f);   // 1/sqrt(24)
        den += ex;
        acc0 += ex * v0; acc1 += ex * v1; acc2 += ex * v2;
        acc3 += ex * v3; acc4 += ex * v4; acc5 += ex * v5;
        float elo = g == 0 ? eav[0] : g == 1 ? eav[2] : g == 2 ? eav[4] : eav[6];
        float ehi = g == 0 ? eav[1] : g == 1 ? eav[3] : g == 2 ? eav[5] : 0.f;
        a0 += ex * elo;
        a1 += ex * ehi;
    }

    float inv = 1.f / den;
    int base = lane & ~3;
    float ae[7];
    ae[0] = __shfl_sync(0xffffffffu, a0, base);
    ae[1] = __shfl_sync(0xffffffffu, a1, base);
    ae[2] = __shfl_sync(0xffffffffu, a0, base + 1);
    ae[3] = __shfl_sync(0xffffffffu, a1, base + 1);
    ae[4] = __shfl_sync(0xffffffffu, a0, base + 2);
    ae[5] = __shfl_sync(0xffffffffu, a1, base + 2);
    ae[6] = __shfl_sync(0xffffffffu, a0, base + 3);

    float m[6] = {acc0, acc1, acc2, acc3, acc4, acc5};
    const float* wb = &sW[tc];
    #pragma unroll
    for (int j = 0; j < 6; j++) {
        #pragma unroll
        for (int t = 0; t < 7; t++) m[j] += ae[t] * wb[t * 192 + j];
    }
    float* outp = (float*)g_acc1 + node * 192 + tc;
    #pragma unroll
    for (int j2 = 0; j2 < 3; j2++) {
        float2 sk = *(float2*)(outp + 2 * j2);
        sk.x += m[2 * j2] * inv;
        sk.y += m[2 * j2 + 1] * inv;
        *(float2*)(outp + 2 * j2) = sk;
    }
}

// ---------------- conv2 node GEMM: elu(acc1) [N,192]@[192,256], f32x2 --------
__global__ __launch_bounds__(256) void k_gemm2(
        const float* __restrict__ qw, const float* __restrict__ qb,
        const float* __restrict__ kw, const float* __restrict__ kb,
        const float* __restrict__ vw, const float* __restrict__ vb,
        const float* __restrict__ sw, const float* __restrict__ sb,
        int n) {
    __shared__ float sT[192 * 36];          // transposed [k][node], pad 36
    int tid = threadIdx.x;                  // 256 threads
    int base = blockIdx.x * 32;
    int cnt  = min(32, n - base);
    {
        int nn = tid & 31, kq = tid >> 5;   // kq 0..7
        #pragma unroll
        for (int j = 0; j < 6; j++) {
            int k4 = kq + 8 * j;
            float4 v = (nn < cnt) ? g_acc1[(base + nn) * 48 + k4] : make_float4(0, 0, 0, 0);
            v.x = eluf(v.x); v.y = eluf(v.y); v.z = eluf(v.z); v.w = eluf(v.w);
            sT[(4 * k4 + 0) * 36 + nn] = v.x;
            sT[(4 * k4 + 1) * 36 + nn] = v.y;
            sT[(4 * k4 + 2) * 36 + nn] = v.z;
            sT[(4 * k4 + 3) * 36 + nn] = v.w;
        }
    }
    __syncthreads();
    int arr = tid >> 6, cc = tid & 63;
    const float* W = arr == 0 ? qw : arr == 1 ? kw : arr == 2 ? vw : sw;
    float bias = (arr == 0 ? qb : arr == 1 ? kb : arr == 2 ? vb : sb)[cc];
    float* op; int stride; int coff = cc;
    if (arr == 0)      { op = (float*)g_q2;  stride = 64; }
    else if (arr == 1) { op = (float*)g_kv2; stride = 128; }
    else if (arr == 2) { op = (float*)g_kv2; stride = 128; coff = 64 + cc; }
    else               { op = (float*)g_acc2; stride = 64; }
    ull acc[16];
    ull b2 = pk2(bias, bias);
    #pragma unroll
    for (int p = 0; p < 16; p++) acc[p] = b2;
    uint32_t sbase = smem_u32(sT);
    #pragma unroll 2
    for (int k = 0; k < 192; k++) {
        float w = W[k * 64 + cc];
        ull w2 = pk2(w, w);
        uint32_t ra = sbase + (uint32_t)(k * 36) * 4u;
        #pragma unroll
        for (int p = 0; p < 8; p++) {
            ull h01, h23;
            lds_v2u64(h01, h23, ra + 16u * p);
            acc[2 * p]     = fma2(h01, w2, acc[2 * p]);
            acc[2 * p + 1] = fma2(h23, w2, acc[2 * p + 1]);
        }
    }
    #pragma unroll
    for (int p = 0; p < 16; p++) {
        float lo, hi; upk2(acc[p], lo, hi);
        int na = 2 * p, nb = na + 1;
        if (na < cnt) op[(size_t)(base + na) * stride + coff] = lo;
        if (nb < cnt) op[(size_t)(base + nb) * stride + coff] = hi;
    }
}

// ---------------- conv2: node-centric fused softmax-aggregate -----------------
__global__ void k_conv2(const float* __restrict__ ea, const float* __restrict__ ew, int n) {
    __shared__ float sW[448];               // e2_w [7,64]
    int tid = threadIdx.x;
    for (int i = tid; i < 448; i += 256) sW[i] = ew[i];
    __syncthreads();
    int node = blockIdx.x * 8 + (tid >> 5);
    int lane = tid & 31;
    if (node >= n) return;
    int deg = g_deg[node];
    if (deg == 0) return;
    int rs = g_rowptr[node];

    const float* qr = (const float*)g_q2 + node * 64 + lane * 2;
    float2 qv = *(const float2*)qr;

    float pqh[7];
    #pragma unroll
    for (int t = 0; t < 7; t++) {
        const float* w = &sW[t * 64 + lane * 2];
        float p = qv.x * w[0] + qv.y * w[1];
        p += __shfl_xor_sync(0xffffffffu, p, 1);
        p += __shfl_xor_sync(0xffffffffu, p, 2);
        pqh[t] = p;
    }

    float acc0 = 0.f, acc1 = 0.f, den = 0.f, a0 = 0.f, a1 = 0.f;
    int g = lane & 3;

    int2 se = g_cpack[rs];
    for (int i = 0; i < deg; i++) {
        int s = se.x, eid = se.y;
        if (i + 1 < deg) se = g_cpack[rs + i + 1];
        float eav[7];
        #pragma unroll
        for (int t = 0; t < 7; t++) eav[t] = __ldg(&ea[eid * 7 + t]);
        const float* kv = (const float*)g_kv2 + s * 128 + lane * 2;
        float2 kk = *(const float2*)kv;
        float2 vv = *(const float2*)(kv + 64);
        float lp = qv.x * kk.x + qv.y * kk.y;
        lp += __shfl_xor_sync(0xffffffffu, lp, 1);
        lp += __shfl_xor_sync(0xffffffffu, lp, 2);
        #pragma unroll
        for (int t = 0; t < 7; t++) lp += eav[t] * pqh[t];
        float ex = __expf(lp * 0.35355339059327373f);   // 1/sqrt(8)
        den += ex;
        acc0 += ex * vv.x;
        acc1 += ex * vv.y;
        float elo = g == 0 ? eav[0] : g == 1 ? eav[2] : g == 2 ? eav[4] : eav[6];
        float ehi = g == 0 ? eav[1] : g == 1 ? eav[3] : g == 2 ? eav[5] : 0.f;
        a0 += ex * elo;
        a1 += ex * ehi;
    }

    float inv = 1.f / den;
    int base = lane & ~3;
    float ae[7];
    ae[0] = __shfl_sync(0xffffffffu, a0, base);
    ae[1] = __shfl_sync(0xffffffffu, a1, base);
    ae[2] = __shfl_sync(0xffffffffu, a0, base + 1);
    ae[3] = __shfl_sync(0xffffffffu, a1, base + 1);
    ae[4] = __shfl_sync(0xffffffffu, a0, base + 2);
    ae[5] = __shfl_sync(0xffffffffu, a1, base + 2);
    ae[6] = __shfl_sync(0xffffffffu, a0, base + 3);

    float m0 = acc0, m1 = acc1;
    const float* wb = &sW[lane * 2];
    #pragma unroll
    for (int t = 0; t < 7; t++) {
        m0 += ae[t] * wb[t * 64];
        m1 += ae[t] * wb[t * 64 + 1];
    }
    float* outp = (float*)g_acc2 + node * 64 + lane * 2;
    float2 sk = *(float2*)outp;
    sk.x += m0 * inv;
    sk.y += m1 * inv;
    *(float2*)outp = sk;
}

// ---------------- head: elu -> lin1(64,20) -> elu -> lin2(20,1), f32x2 -------
__global__ void k_final(const float* __restrict__ w1, const float* __restrict__ b1,
                        const float* __restrict__ w2, const float* __restrict__ b2,
                        float* __restrict__ out, int n) {
    __shared__ float sw1t[20 * 64];         // transposed [j][k]
    __shared__ float sb1[20], sw2[20], sb2v[1];
    int tid = threadIdx.x;
    for (int i = tid; i < 1280; i += 256) {
        int k = i / 20, j = i % 20;
        sw1t[j * 64 + k] = w1[i];
    }
    if (tid < 20) { sb1[tid] = b1[tid]; sw2[tid] = w2[tid]; }
    if (tid == 0) sb2v[0] = b2[0];
    __syncthreads();
    int node = blockIdx.x * 256 + tid;
    if (node >= n) return;
    ull hp[32];
    const float4* r = g_acc2 + node * 16;
    #pragma unroll
    for (int i = 0; i < 16; i++) {
        float4 v = r[i];
        hp[2 * i]     = pk2(eluf(v.x), eluf(v.y));
        hp[2 * i + 1] = pk2(eluf(v.z), eluf(v.w));
    }
    uint32_t sbase = smem_u32(sw1t);
    float res = sb2v[0];
    #pragma unroll 2
    for (int j = 0; j < 20; j++) {
        ull a2 = 0;
        uint32_t ra = sbase + (uint32_t)j * 256u;
        #pragma unroll
        for (int kk = 0; kk < 32; kk++) {
            ull w2p = lds_u64(ra + 8u * kk);
            a2 = fma2(hp[kk], w2p, a2);
        }
        float lo, hi; upk2(a2, lo, hi);
        res += eluf(sb1[j] + lo + hi) * sw2[j];
    }
    out[node] = res;
}

// ---------------- host launcher ----------------------------------------------
extern "C" void kernel_launch(void* const* d_in, const int* in_sizes, int n_in,
                              void* d_out, int out_size) {
    const float* x      = (const float*)d_in[0];
    const int*   ei     = (const int*)  d_in[1];
    const float* ea     = (const float*)d_in[2];
    const float* linA_w = (const float*)d_in[3];
    const float* linA_b = (const float*)d_in[4];
    const float* linB_w = (const float*)d_in[5];
    const float* linB_b = (const float*)d_in[6];
    const float* q1_w   = (const float*)d_in[7];
    const float* q1_b   = (const float*)d_in[8];
    const float* k1_w   = (const float*)d_in[9];
    const float* k1_b   = (const float*)d_in[10];
    const float* v1_w   = (const float*)d_in[11];
    const float* v1_b   = (const float*)d_in[12];
    const float* e1_w   = (const float*)d_in[13];
    const float* s1_w   = (const float*)d_in[14];
    const float* s1_b   = (const float*)d_in[15];
    const float* q2_w   = (const float*)d_in[16];
    const float* q2_b   = (const float*)d_in[17];
    const float* k2_w   = (const float*)d_in[18];
    const float* k2_b   = (const float*)d_in[19];
    const float* v2_w   = (const float*)d_in[20];
    const float* v2_b   = (const float*)d_in[21];
    const float* e2_w   = (const float*)d_in[22];
    const float* s2_w   = (const float*)d_in[23];
    const float* s2_b   = (const float*)d_in[24];
    const float* lin1_w = (const float*)d_in[25];
    const float* lin1_b = (const float*)d_in[26];
    const float* lin2_w = (const float*)d_in[27];
    const float* lin2_b = (const float*)d_in[28];

    int n = in_sizes[0] / 23;
    int E = in_sizes[1] / 2;
    const int* src = ei;
    const int* dst = ei + E;
    float* out = (float*)d_out;

    int nb256  = (n + 255) / 256;
    int eb256  = (E + 255) / 256;
    int nbconv = (n + 7) / 8;

    // keep k_gemm1 at launch index 3 (the ncu capture slot) for predict-verify
    k_zero   <<<nb256, 256>>>(n);
    k_count  <<<eb256, 256>>>(dst, E);
    k_h2     <<<nb256, 256>>>(x, linA_w, linA_b, linB_w, linB_b, n);
    k_gemm1  <<<(n + 127) / 128, 768>>>(q1_w, q1_b, k1_w, k1_b, v1_w, v1_b, s1_w, s1_b, n);
    k_scanA  <<<nb256, 256>>>(n);
    k_scanB  <<<1, 512>>>(nb256);
    k_scanC  <<<nb256, 256>>>(n);
    k_scatter<<<eb256, 256>>>(src, dst, E);
    k_conv1  <<<nbconv, 256>>>(ea, e1_w, n);
    k_gemm2  <<<(n + 31) / 32, 256>>>(q2_w, q2_b, k2_w, k2_b, v2_w, v2_b, s2_w, s2_b, n);
    k_conv2  <<<nbconv, 256>>>(ea, e2_w, n);
    k_final  <<<nb256, 256>>>(lin1_w, lin1_b, lin2_w, lin2_b, out, n);
}